// round 2
// baseline (speedup 1.0000x reference)
#include <cuda_runtime.h>

#define N_TRACK 50000
#define N_LANE  50000
#define N_ATT   100000
#define NP_T    1000000
#define NP_L    500000
#define E_ATT   1600000
#define HEADS   30
#define D_OUT   2
#define NEG_SLOPE 0.2f
#define LN_EPS  1e-5f

// ---------------- static scratch (no allocations allowed) ----------------
__device__ float g_track_pool[N_TRACK * 4];   // 0.8 MB
__device__ float g_lane_pool [N_LANE  * 2];   // 0.4 MB
__device__ float g_feats     [N_ATT * 10];    // 4  MB
__device__ float g_h         [N_ATT * 60];    // 24 MB (L2-resident in GAT phase)
__device__ float g_el        [N_ATT * HEADS]; // 12 MB
__device__ int   g_off       [N_ATT + 1];     // CSR offsets over sorted att_dst

// ---------------- K0: zero the pools (must happen every replay) ----------
__global__ void k_zero_pools() {
    int i = blockIdx.x * blockDim.x + threadIdx.x;
    int nt = N_TRACK * 4;
    if (i < nt) g_track_pool[i] = 0.f;
    else if (i < nt + N_LANE * 2) g_lane_pool[i - nt] = 0.f;
}

// ---------------- K1: track point MLP + segment max (atomicMax) ----------
__global__ void k_track_points(const float4* __restrict__ x,
                               const int*    __restrict__ tid,
                               const float*  __restrict__ W,
                               const float*  __restrict__ b,
                               const float*  __restrict__ g,
                               const float*  __restrict__ beta) {
    int i = blockIdx.x * blockDim.x + threadIdx.x;
    if (i >= NP_T) return;
    float4 p = x[i];
    float h[4];
#pragma unroll
    for (int j = 0; j < 4; j++)
        h[j] = p.x * __ldg(&W[0 * 4 + j]) + p.y * __ldg(&W[1 * 4 + j]) +
               p.z * __ldg(&W[2 * 4 + j]) + p.w * __ldg(&W[3 * 4 + j]) + __ldg(&b[j]);
    float mu = 0.25f * (h[0] + h[1] + h[2] + h[3]);
    float var = 0.f;
#pragma unroll
    for (int j = 0; j < 4; j++) { float d = h[j] - mu; var += d * d; }
    var *= 0.25f;
    float inv = rsqrtf(var + LN_EPS);
    int t = tid[i];
    unsigned int* pool = reinterpret_cast<unsigned int*>(&g_track_pool[t * 4]);
#pragma unroll
    for (int j = 0; j < 4; j++) {
        float v = (h[j] - mu) * inv * __ldg(&g[j]) + __ldg(&beta[j]);
        v = fmaxf(v, 0.f);                       // ReLU: v >= 0 so uint-max == float-max
        atomicMax(&pool[j], __float_as_uint(v));
    }
}

// ---------------- K2: lane point MLP + segment max ------------------------
__global__ void k_lane_points(const float2* __restrict__ x,
                              const int*    __restrict__ lid,
                              const float*  __restrict__ W,
                              const float*  __restrict__ b,
                              const float*  __restrict__ g,
                              const float*  __restrict__ beta) {
    int i = blockIdx.x * blockDim.x + threadIdx.x;
    if (i >= NP_L) return;
    float2 p = x[i];
    float h0 = p.x * __ldg(&W[0]) + p.y * __ldg(&W[2]) + __ldg(&b[0]);
    float h1 = p.x * __ldg(&W[1]) + p.y * __ldg(&W[3]) + __ldg(&b[1]);
    float mu = 0.5f * (h0 + h1);
    float d0 = h0 - mu, d1 = h1 - mu;
    float var = 0.5f * (d0 * d0 + d1 * d1);
    float inv = rsqrtf(var + LN_EPS);
    int t = lid[i];
    unsigned int* pool = reinterpret_cast<unsigned int*>(&g_lane_pool[t * 2]);
    float v0 = fmaxf(d0 * inv * __ldg(&g[0]) + __ldg(&beta[0]), 0.f);
    float v1 = fmaxf(d1 * inv * __ldg(&g[1]) + __ldg(&beta[1]), 0.f);
    atomicMax(&pool[0], __float_as_uint(v0));
    atomicMax(&pool[1], __float_as_uint(v1));
}

// ---------------- K3a: feats = pool @ out_W + b  (thread per (n,j)) -------
__global__ void k_feats(const float* __restrict__ tW, const float* __restrict__ tb,
                        const float* __restrict__ lW, const float* __restrict__ lb) {
    int idx = blockIdx.x * blockDim.x + threadIdx.x;
    if (idx >= N_ATT * 10) return;
    int n = idx / 10, j = idx - n * 10;
    float acc;
    if (n < N_TRACK) {
        const float* p = &g_track_pool[n * 4];
        acc = __ldg(&tb[j]);
#pragma unroll
        for (int k = 0; k < 4; k++) acc += p[k] * __ldg(&tW[k * 10 + j]);
    } else {
        const float* p = &g_lane_pool[(n - N_TRACK) * 2];
        acc = __ldg(&lb[j]);
#pragma unroll
        for (int k = 0; k < 2; k++) acc += p[k] * __ldg(&lW[k * 10 + j]);
    }
    g_feats[idx] = acc;
}

// ---------------- K3b: h = feats @ fc_W  (thread per (n,j), j<60) ---------
__global__ void k_h(const float* __restrict__ fcW) {
    int idx = blockIdx.x * blockDim.x + threadIdx.x;
    if (idx >= N_ATT * 60) return;
    int n = idx / 60, j = idx - n * 60;
    const float* f = &g_feats[n * 10];
    float acc = 0.f;
#pragma unroll
    for (int k = 0; k < 10; k++) acc += f[k] * __ldg(&fcW[k * 60 + j]);
    g_h[idx] = acc;
}

// ---------------- K3c: el[n,h] = h[n,h,:] . attn_l[h,:] -------------------
__global__ void k_el(const float* __restrict__ al) {
    int idx = blockIdx.x * blockDim.x + threadIdx.x;
    if (idx >= N_ATT * HEADS) return;
    int n = idx / HEADS, j = idx - n * HEADS;
    g_el[idx] = g_h[n * 60 + 2 * j] * __ldg(&al[2 * j]) +
                g_h[n * 60 + 2 * j + 1] * __ldg(&al[2 * j + 1]);
}

// ---------------- K_off: CSR offsets from sorted att_dst ------------------
__global__ void k_offsets(const int* __restrict__ dst) {
    int e = blockIdx.x * blockDim.x + threadIdx.x;
    if (e < E_ATT) {
        int cur = dst[e];
        int prev = (e == 0) ? -1 : dst[e - 1];
        for (int d = prev + 1; d <= cur; ++d) g_off[d] = e;
    } else if (e == E_ATT) {
        int last = dst[E_ATT - 1];
        for (int d = last + 1; d <= N_ATT; ++d) g_off[d] = E_ATT;
    }
}

// ---------------- K4: GAT — warp per dst, lane = head, online softmax -----
__global__ void __launch_bounds__(256)
k_gat(const int* __restrict__ src,
      const float* __restrict__ ar,
      const float* __restrict__ bias,
      float* __restrict__ out) {
    int warp = (blockIdx.x * blockDim.x + threadIdx.x) >> 5;
    int lane = threadIdx.x & 31;
    if (warp >= N_TRACK) return;       // only track destinations produce output
    int d = warp;
    if (lane >= HEADS) return;

    int s0 = g_off[d], s1 = g_off[d + 1];

    float er = g_h[d * 60 + 2 * lane]     * __ldg(&ar[2 * lane]) +
               g_h[d * 60 + 2 * lane + 1] * __ldg(&ar[2 * lane + 1]);

    float m = -1e30f, den = 0.f, n0 = 0.f, n1 = 0.f;
    for (int e = s0; e < s1; ++e) {
        int s = __ldg(&src[e]);                       // broadcast across lanes
        float v = g_el[s * HEADS + lane] + er;        // coalesced 120B gather
        v = v > 0.f ? v : NEG_SLOPE * v;              // leaky_relu
        float mn = fmaxf(m, v);
        float sc = __expf(m - mn);                    // first iter: exp(-huge)=0
        float ee = __expf(v - mn);
        const float* hs = &g_h[s * 60];               // coalesced 240B gather
        den = den * sc + ee;
        n0  = n0  * sc + ee * hs[2 * lane];
        n1  = n1  * sc + ee * hs[2 * lane + 1];
        m = mn;
    }
    float o0, o1;
    if (s1 > s0) {
        float r = 1.f / den;
        o0 = n0 * r + __ldg(&bias[2 * lane]);
        o1 = n1 * r + __ldg(&bias[2 * lane + 1]);
    } else {                                          // empty segment -> just bias
        o0 = __ldg(&bias[2 * lane]);
        o1 = __ldg(&bias[2 * lane + 1]);
    }
    out[d * 60 + 2 * lane]     = o0;
    out[d * 60 + 2 * lane + 1] = o1;
}

// ---------------------------------------------------------------------------
extern "C" void kernel_launch(void* const* d_in, const int* in_sizes, int n_in,
                              void* d_out, int out_size) {
    const float4* track_pts = (const float4*)d_in[0];
    const float2* lane_pts  = (const float2*)d_in[1];
    const int*    pt_tid    = (const int*)d_in[2];
    const int*    pt_lid    = (const int*)d_in[3];
    const int*    att_src   = (const int*)d_in[4];
    const int*    att_dst   = (const int*)d_in[5];
    const float*  t_mlp_W   = (const float*)d_in[6];
    const float*  t_mlp_b   = (const float*)d_in[7];
    const float*  t_ln_g    = (const float*)d_in[8];
    const float*  t_ln_b    = (const float*)d_in[9];
    const float*  t_out_W   = (const float*)d_in[10];
    const float*  t_out_b   = (const float*)d_in[11];
    const float*  l_mlp_W   = (const float*)d_in[12];
    const float*  l_mlp_b   = (const float*)d_in[13];
    const float*  l_ln_g    = (const float*)d_in[14];
    const float*  l_ln_b    = (const float*)d_in[15];
    const float*  l_out_W   = (const float*)d_in[16];
    const float*  l_out_b   = (const float*)d_in[17];
    const float*  gat_fc_W  = (const float*)d_in[18];
    const float*  gat_al    = (const float*)d_in[19];
    const float*  gat_ar    = (const float*)d_in[20];
    const float*  gat_bias  = (const float*)d_in[21];
    float* out = (float*)d_out;

    const int T = 256;
    k_zero_pools<<<(N_TRACK * 4 + N_LANE * 2 + T - 1) / T, T>>>();
    k_track_points<<<(NP_T + T - 1) / T, T>>>(track_pts, pt_tid, t_mlp_W, t_mlp_b, t_ln_g, t_ln_b);
    k_lane_points <<<(NP_L + T - 1) / T, T>>>(lane_pts, pt_lid, l_mlp_W, l_mlp_b, l_ln_g, l_ln_b);
    k_offsets<<<(E_ATT + 1 + T - 1) / T, T>>>(att_dst);   // independent of pools; overlaps fine
    k_feats<<<(N_ATT * 10 + T - 1) / T, T>>>(t_out_W, t_out_b, l_out_W, l_out_b);
    k_h    <<<(N_ATT * 60 + T - 1) / T, T>>>(gat_fc_W);
    k_el   <<<(N_ATT * HEADS + T - 1) / T, T>>>(gat_al);
    k_gat  <<<(N_TRACK * 32 + T - 1) / T, T>>>(att_src, gat_ar, gat_bias, out);
}

// round 3
// speedup vs baseline: 1.5270x; 1.5270x over previous
#include <cuda_runtime.h>

#define N_TRACK 50000
#define N_LANE  50000
#define N_ATT   100000
#define NP_T    1000000
#define NP_L    500000
#define E_ATT   1600000
#define HEADS   30
#define NEG_SLOPE 0.2f
#define LN_EPS  1e-5f

// ---------------- static scratch (no allocations allowed) ----------------
__device__ float g_track_pool[N_TRACK * 4];   // 0.8 MB
__device__ float g_lane_pool [N_LANE  * 2];   // 0.4 MB
__device__ float g_h         [N_ATT * 60];    // 24 MB (L2-resident in GAT phase)
__device__ int   g_off       [N_ATT + 1];     // CSR offsets over sorted att_dst

// ---------------- K0: zero the pools (must happen every replay) ----------
__global__ void k_zero_pools() {
    int i = blockIdx.x * blockDim.x + threadIdx.x;
    int nt = N_TRACK * 4;
    if (i < nt) g_track_pool[i] = 0.f;
    else if (i < nt + N_LANE * 2) g_lane_pool[i - nt] = 0.f;
}

// ---------------- K1: track point MLP + warp-aggregated segment max -------
__global__ void k_track_points(const float4* __restrict__ x,
                               const int*    __restrict__ tid,
                               const float*  __restrict__ W,
                               const float*  __restrict__ b,
                               const float*  __restrict__ g,
                               const float*  __restrict__ beta) {
    int i = blockIdx.x * blockDim.x + threadIdx.x;
    int lane = threadIdx.x & 31;
    int t = -1;
    float v[4] = {0.f, 0.f, 0.f, 0.f};
    if (i < NP_T) {
        float4 p = x[i];
        float h[4];
#pragma unroll
        for (int j = 0; j < 4; j++)
            h[j] = p.x * __ldg(&W[0 * 4 + j]) + p.y * __ldg(&W[1 * 4 + j]) +
                   p.z * __ldg(&W[2 * 4 + j]) + p.w * __ldg(&W[3 * 4 + j]) + __ldg(&b[j]);
        float mu = 0.25f * (h[0] + h[1] + h[2] + h[3]);
        float var = 0.f;
#pragma unroll
        for (int j = 0; j < 4; j++) { float d = h[j] - mu; var += d * d; }
        float inv = rsqrtf(var * 0.25f + LN_EPS);
        t = tid[i];
#pragma unroll
        for (int j = 0; j < 4; j++)
            v[j] = fmaxf((h[j] - mu) * inv * __ldg(&g[j]) + __ldg(&beta[j]), 0.f);
    }
    // segmented max-scan: collect max from higher lanes with the same id
#pragma unroll
    for (int off = 1; off < 32; off <<= 1) {
        int t2 = __shfl_down_sync(0xffffffffu, t, off);
        float u0 = __shfl_down_sync(0xffffffffu, v[0], off);
        float u1 = __shfl_down_sync(0xffffffffu, v[1], off);
        float u2 = __shfl_down_sync(0xffffffffu, v[2], off);
        float u3 = __shfl_down_sync(0xffffffffu, v[3], off);
        if (lane + off < 32 && t2 == t) {
            v[0] = fmaxf(v[0], u0); v[1] = fmaxf(v[1], u1);
            v[2] = fmaxf(v[2], u2); v[3] = fmaxf(v[3], u3);
        }
    }
    int tprev = __shfl_up_sync(0xffffffffu, t, 1);
    bool head = (lane == 0) || (tprev != t);
    if (head && t >= 0) {
        unsigned int* pool = reinterpret_cast<unsigned int*>(&g_track_pool[t * 4]);
#pragma unroll
        for (int j = 0; j < 4; j++) atomicMax(&pool[j], __float_as_uint(v[j]));
    }
}

// ---------------- K2: lane point MLP + warp-aggregated segment max --------
__global__ void k_lane_points(const float2* __restrict__ x,
                              const int*    __restrict__ lid,
                              const float*  __restrict__ W,
                              const float*  __restrict__ b,
                              const float*  __restrict__ g,
                              const float*  __restrict__ beta) {
    int i = blockIdx.x * blockDim.x + threadIdx.x;
    int lane = threadIdx.x & 31;
    int t = -1;
    float v0 = 0.f, v1 = 0.f;
    if (i < NP_L) {
        float2 p = x[i];
        float h0 = p.x * __ldg(&W[0]) + p.y * __ldg(&W[2]) + __ldg(&b[0]);
        float h1 = p.x * __ldg(&W[1]) + p.y * __ldg(&W[3]) + __ldg(&b[1]);
        float mu = 0.5f * (h0 + h1);
        float d0 = h0 - mu, d1 = h1 - mu;
        float inv = rsqrtf(0.5f * (d0 * d0 + d1 * d1) + LN_EPS);
        t = lid[i];
        v0 = fmaxf(d0 * inv * __ldg(&g[0]) + __ldg(&beta[0]), 0.f);
        v1 = fmaxf(d1 * inv * __ldg(&g[1]) + __ldg(&beta[1]), 0.f);
    }
#pragma unroll
    for (int off = 1; off < 32; off <<= 1) {
        int t2 = __shfl_down_sync(0xffffffffu, t, off);
        float u0 = __shfl_down_sync(0xffffffffu, v0, off);
        float u1 = __shfl_down_sync(0xffffffffu, v1, off);
        if (lane + off < 32 && t2 == t) { v0 = fmaxf(v0, u0); v1 = fmaxf(v1, u1); }
    }
    int tprev = __shfl_up_sync(0xffffffffu, t, 1);
    bool head = (lane == 0) || (tprev != t);
    if (head && t >= 0) {
        unsigned int* pool = reinterpret_cast<unsigned int*>(&g_lane_pool[t * 2]);
        atomicMax(&pool[0], __float_as_uint(v0));
        atomicMax(&pool[1], __float_as_uint(v1));
    }
}

// ---------------- K_off: CSR offsets from sorted att_dst (int4) -----------
__global__ void k_offsets(const int* __restrict__ dst) {
    int q = blockIdx.x * blockDim.x + threadIdx.x;     // quad index
    if (q >= E_ATT / 4) return;
    int4 d4 = __ldg((const int4*)dst + q);
    int e0 = q * 4;
    int prev = (q == 0) ? -1 : __ldg(&dst[e0 - 1]);
    int cur[4] = {d4.x, d4.y, d4.z, d4.w};
#pragma unroll
    for (int k = 0; k < 4; k++) {
        for (int d = prev + 1; d <= cur[k]; ++d) g_off[d] = e0 + k;
        prev = cur[k];
    }
    if (e0 + 4 == E_ATT) {
        for (int d = prev + 1; d <= N_ATT; ++d) g_off[d] = E_ATT;
    }
}

// ---------------- K3: fused feats + h  (block of 256 handles 64 nodes) ----
__global__ void __launch_bounds__(256)
k_node(const float* __restrict__ tW, const float* __restrict__ tb,
       const float* __restrict__ lW, const float* __restrict__ lb,
       const float* __restrict__ fcW) {
    __shared__ float sf[64 * 10];      // feats for 64 nodes
    __shared__ float sW[10 * 60];      // gat_fc_W
    int t = threadIdx.x;
    int n0 = blockIdx.x * 64;
    for (int i = t; i < 600; i += 256) sW[i] = __ldg(&fcW[i]);
    if (t < 64) {
        int n = n0 + t;
        if (n < N_ATT) {
            if (n < N_TRACK) {
                const float* p = &g_track_pool[n * 4];
#pragma unroll
                for (int j = 0; j < 10; j++) {
                    float acc = __ldg(&tb[j]);
#pragma unroll
                    for (int k = 0; k < 4; k++) acc += p[k] * __ldg(&tW[k * 10 + j]);
                    sf[t * 10 + j] = acc;
                }
            } else {
                const float* p = &g_lane_pool[(n - N_TRACK) * 2];
#pragma unroll
                for (int j = 0; j < 10; j++) {
                    float acc = __ldg(&lb[j]);
                    acc += p[0] * __ldg(&lW[j]) + p[1] * __ldg(&lW[10 + j]);
                    sf[t * 10 + j] = acc;
                }
            }
        }
    }
    __syncthreads();
#pragma unroll
    for (int r = 0; r < 15; r++) {                     // 64*60 / 256 = 15
        int i = r * 256 + t;
        int ln = i / 60, j = i - ln * 60;
        int n = n0 + ln;
        if (n >= N_ATT) break;
        const float* f = &sf[ln * 10];
        float acc = 0.f;
#pragma unroll
        for (int k = 0; k < 10; k++) acc += f[k] * sW[k * 60 + j];
        g_h[n * 60 + j] = acc;
    }
}

// ---------------- K4: GAT — warp per dst, lane = head, online softmax -----
// el[s] recomputed from the already-gathered h values (no g_el array).
__global__ void __launch_bounds__(256)
k_gat(const int* __restrict__ src,
      const float* __restrict__ al,
      const float* __restrict__ ar,
      const float* __restrict__ bias,
      float* __restrict__ out) {
    int warp = (blockIdx.x * blockDim.x + threadIdx.x) >> 5;
    int lane = threadIdx.x & 31;
    if (warp >= N_TRACK) return;           // only track destinations are output
    int d = warp;
    int hl = lane < HEADS ? lane : HEADS - 1;   // keep all 32 lanes alive for shfl

    float al0 = __ldg(&al[2 * hl]), al1 = __ldg(&al[2 * hl + 1]);
    float er = g_h[d * 60 + 2 * hl]     * __ldg(&ar[2 * hl]) +
               g_h[d * 60 + 2 * hl + 1] * __ldg(&ar[2 * hl + 1]);

    int s0 = g_off[d], s1 = g_off[d + 1];
    float m = -1e30f, den = 0.f, acc0 = 0.f, acc1 = 0.f;

    for (int base = s0; base < s1; base += 32) {
        int cnt = s1 - base; if (cnt > 32) cnt = 32;
        int my = (lane < cnt) ? __ldg(&src[base + lane]) : 0;   // coalesced batch
        for (int k = 0; k < cnt; k++) {
            int s = __shfl_sync(0xffffffffu, my, k);
            float hs0 = g_h[s * 60 + 2 * hl];
            float hs1 = g_h[s * 60 + 2 * hl + 1];
            float v = hs0 * al0 + hs1 * al1 + er;               // el[s] + er[d]
            v = v > 0.f ? v : NEG_SLOPE * v;                    // leaky_relu
            float mn = fmaxf(m, v);
            float sc = __expf(m - mn);                          // first iter: 0
            float ee = __expf(v - mn);
            den  = den  * sc + ee;
            acc0 = acc0 * sc + ee * hs0;
            acc1 = acc1 * sc + ee * hs1;
            m = mn;
        }
    }
    if (lane < HEADS) {
        float o0, o1;
        if (s1 > s0) {
            float r = 1.f / den;
            o0 = acc0 * r + __ldg(&bias[2 * lane]);
            o1 = acc1 * r + __ldg(&bias[2 * lane + 1]);
        } else {
            o0 = __ldg(&bias[2 * lane]);
            o1 = __ldg(&bias[2 * lane + 1]);
        }
        out[d * 60 + 2 * lane]     = o0;
        out[d * 60 + 2 * lane + 1] = o1;
    }
}

// ---------------------------------------------------------------------------
extern "C" void kernel_launch(void* const* d_in, const int* in_sizes, int n_in,
                              void* d_out, int out_size) {
    const float4* track_pts = (const float4*)d_in[0];
    const float2* lane_pts  = (const float2*)d_in[1];
    const int*    pt_tid    = (const int*)d_in[2];
    const int*    pt_lid    = (const int*)d_in[3];
    const int*    att_src   = (const int*)d_in[4];
    const int*    att_dst   = (const int*)d_in[5];
    const float*  t_mlp_W   = (const float*)d_in[6];
    const float*  t_mlp_b   = (const float*)d_in[7];
    const float*  t_ln_g    = (const float*)d_in[8];
    const float*  t_ln_b    = (const float*)d_in[9];
    const float*  t_out_W   = (const float*)d_in[10];
    const float*  t_out_b   = (const float*)d_in[11];
    const float*  l_mlp_W   = (const float*)d_in[12];
    const float*  l_mlp_b   = (const float*)d_in[13];
    const float*  l_ln_g    = (const float*)d_in[14];
    const float*  l_ln_b    = (const float*)d_in[15];
    const float*  l_out_W   = (const float*)d_in[16];
    const float*  l_out_b   = (const float*)d_in[17];
    const float*  gat_fc_W  = (const float*)d_in[18];
    const float*  gat_al    = (const float*)d_in[19];
    const float*  gat_ar    = (const float*)d_in[20];
    const float*  gat_bias  = (const float*)d_in[21];
    float* out = (float*)d_out;

    const int T = 256;
    k_zero_pools<<<(N_TRACK * 4 + N_LANE * 2 + T - 1) / T, T>>>();
    k_track_points<<<(NP_T + T - 1) / T, T>>>(track_pts, pt_tid, t_mlp_W, t_mlp_b, t_ln_g, t_ln_b);
    k_lane_points <<<(NP_L + T - 1) / T, T>>>(lane_pts, pt_lid, l_mlp_W, l_mlp_b, l_ln_g, l_ln_b);
    k_offsets<<<(E_ATT / 4 + T - 1) / T, T>>>(att_dst);
    k_node<<<(N_ATT + 63) / 64, T>>>(t_out_W, t_out_b, l_out_W, l_out_b, gat_fc_W);
    k_gat<<<(N_TRACK * 32 + T - 1) / T, T>>>(att_src, gat_al, gat_ar, gat_bias, out);
}